// round 1
// baseline (speedup 1.0000x reference)
#include <cuda_runtime.h>
#include <math.h>

// Problem constants
#define Bb    2
#define Ts    2048
#define Hq    32
#define Hkv   8
#define Dd    128
#define INNER 4096
#define KVIN  1024
#define ATTN_SCALE 0.08838834764831845f  // 1/sqrt(128)

// Scratch (device globals: allocation-free scratch per harness rules)
__device__ float g_q[Bb*Ts*Hq*Dd];    // 64 MB
__device__ float g_k[Bb*Ts*Hkv*Dd];   // 16 MB
__device__ float g_v[Bb*Ts*Hkv*Dd];   // 16 MB
__device__ float g_o[Bb*Ts*Hq*Dd];    // 64 MB

// ---------------------------------------------------------------------------
// SGEMM: C[M,N] = A[M,K] @ B[K,N], all row-major fp32.
// 128x128 block, BK=16, 256 threads, 8x8 register tile per thread.
// ---------------------------------------------------------------------------
#define GBM 128
#define GBN 128
#define GBK 16
__global__ __launch_bounds__(256) void sgemm_kernel(
    const float* __restrict__ A, const float* __restrict__ B,
    float* __restrict__ C, int M, int N, int K)
{
    __shared__ float As[GBK][GBM];  // transposed A tile
    __shared__ float Bs[GBK][GBN];

    const int tid = threadIdx.x;
    const int tx  = tid & 15;       // 0..15  -> N direction
    const int ty  = tid >> 4;       // 0..15  -> M direction
    const int rowBase = blockIdx.y * GBM;
    const int colBase = blockIdx.x * GBN;

    float acc[8][8];
    #pragma unroll
    for (int i = 0; i < 8; i++)
        #pragma unroll
        for (int j = 0; j < 8; j++) acc[i][j] = 0.0f;

    for (int k0 = 0; k0 < K; k0 += GBK) {
        // Load A tile (128x16) and B tile (16x128): 512 float4 each, 2 per thread.
        #pragma unroll
        for (int l = 0; l < 2; l++) {
            int idx  = tid + l * 256;
            int aRow = idx >> 2;
            int aCol = (idx & 3) << 2;
            float4 av = *(const float4*)&A[(size_t)(rowBase + aRow) * K + k0 + aCol];
            As[aCol + 0][aRow] = av.x;
            As[aCol + 1][aRow] = av.y;
            As[aCol + 2][aRow] = av.z;
            As[aCol + 3][aRow] = av.w;
            int bRow = idx >> 5;
            int bCol = (idx & 31) << 2;
            *(float4*)&Bs[bRow][bCol] =
                *(const float4*)&B[(size_t)(k0 + bRow) * N + colBase + bCol];
        }
        __syncthreads();

        #pragma unroll
        for (int kk = 0; kk < GBK; kk++) {
            float ra[8], rb[8];
            #pragma unroll
            for (int i = 0; i < 8; i++) ra[i] = As[kk][ty * 8 + i];
            #pragma unroll
            for (int j = 0; j < 8; j++) rb[j] = Bs[kk][tx * 8 + j];
            #pragma unroll
            for (int i = 0; i < 8; i++)
                #pragma unroll
                for (int j = 0; j < 8; j++)
                    acc[i][j] += ra[i] * rb[j];
        }
        __syncthreads();
    }

    #pragma unroll
    for (int i = 0; i < 8; i++) {
        int r = rowBase + ty * 8 + i;
        #pragma unroll
        for (int j = 0; j < 8; j += 4) {
            float4 v = make_float4(acc[i][j], acc[i][j+1], acc[i][j+2], acc[i][j+3]);
            *(float4*)&C[(size_t)r * N + colBase + tx * 8 + j] = v;
        }
    }
}

// ---------------------------------------------------------------------------
// RoPE (rotate-half), in-place. One thread handles a (d, d+64) pair -> no race.
// buf layout: (B, T, HH, 128). cos/sin: (T, 128).
// ---------------------------------------------------------------------------
__global__ void rope_kernel(float* __restrict__ buf,
                            const float* __restrict__ cs,
                            const float* __restrict__ sn,
                            int HH, int nPairs)
{
    int idx = blockIdx.x * blockDim.x + threadIdx.x;
    if (idx >= nPairs) return;
    int d    = idx & 63;
    int rest = idx >> 6;            // (b*T + t)*HH + h
    int t    = (rest / HH) % Ts;
    size_t base = (size_t)rest * 128;
    float l = buf[base + d];
    float r = buf[base + d + 64];
    float c0 = cs[t * 128 + d],      s0 = sn[t * 128 + d];
    float c1 = cs[t * 128 + d + 64], s1 = sn[t * 128 + d + 64];
    buf[base + d]      = l * c0 - r * s0;  // x2 lower half = -r
    buf[base + d + 64] = r * c1 + l * s1;  // x2 upper half = +l
}

// ---------------------------------------------------------------------------
// Flash-style causal GQA attention, fp32.
// Block: 256 threads handles 64 query rows of one (b, h). Key tiles of 32.
// Thread t: rows r0 = t>>3 and r1 = r0+32; S-cols jj = (t&7)*4 .. +3;
//           O-cols d = (t&7) + 8*c, c in [0,16).
// smem strides padded to kill bank conflicts (Qs:130, KVs:129, Ps:33).
// ---------------------------------------------------------------------------
#define ATTN_SMEM ((64*130 + 32*129 + 64*33) * 4)

__global__ __launch_bounds__(256) void attn_kernel()
{
    extern __shared__ float sm[];
    float* Qs  = sm;               // 64 x 130
    float* KVs = Qs + 64 * 130;    // 32 x 129 (K, then reused for V)
    float* Ps  = KVs + 32 * 129;   // 64 x 33

    const int tid   = threadIdx.x;
    const int qb    = blockIdx.x;
    const int h     = blockIdx.y;
    const int b     = blockIdx.z;
    const int qBase = qb * 64;
    const int hk    = h >> 2;      // GQA: 4 query heads per kv head
    const int r0    = tid >> 3;
    const int r1    = r0 + 32;
    const int j4    = tid & 7;
    const int jj    = j4 * 4;

    // Load Q tile
    for (int idx = tid; idx < 64 * 128; idx += 256) {
        int r = idx >> 7, d = idx & 127;
        Qs[r * 130 + d] = g_q[((size_t)(b * Ts + qBase + r) * Hq + h) * Dd + d];
    }

    float acc[2][16];
    #pragma unroll
    for (int c = 0; c < 16; c++) { acc[0][c] = 0.0f; acc[1][c] = 0.0f; }
    float m0 = -INFINITY, m1 = -INFINITY, l0 = 0.0f, l1 = 0.0f;

    const int nTiles = qb * 2 + 2;  // causal: keys up to qBase+63
    for (int kt = 0; kt < nTiles; kt++) {
        __syncthreads();  // prior PV done reading KVs before we overwrite
        // Load K tile
        for (int idx = tid; idx < 32 * 128; idx += 256) {
            int r = idx >> 7, d = idx & 127;
            KVs[r * 129 + d] = g_k[((size_t)(b * Ts + kt * 32 + r) * Hkv + hk) * Dd + d];
        }
        __syncthreads();

        // S = Q @ K^T  (2 rows x 4 cols per thread)
        float s0[4] = {0,0,0,0}, s1[4] = {0,0,0,0};
        #pragma unroll 4
        for (int d = 0; d < 128; d++) {
            float q0 = Qs[r0 * 130 + d];
            float q1 = Qs[r1 * 130 + d];
            #pragma unroll
            for (int c = 0; c < 4; c++) {
                float kv = KVs[(jj + c) * 129 + d];
                s0[c] += q0 * kv;
                s1[c] += q1 * kv;
            }
        }

        // Scale + causal mask (matches reference: masked = exactly -30000)
        #pragma unroll
        for (int c = 0; c < 4; c++) {
            int jg = kt * 32 + jj + c;
            s0[c] = (jg <= qBase + r0) ? s0[c] * ATTN_SCALE : -30000.0f;
            s1[c] = (jg <= qBase + r1) ? s1[c] * ATTN_SCALE : -30000.0f;
        }

        // Row max across the 8 lanes owning this row
        float bm0 = fmaxf(fmaxf(s0[0], s0[1]), fmaxf(s0[2], s0[3]));
        float bm1 = fmaxf(fmaxf(s1[0], s1[1]), fmaxf(s1[2], s1[3]));
        #pragma unroll
        for (int o = 1; o < 8; o <<= 1) {
            bm0 = fmaxf(bm0, __shfl_xor_sync(0xffffffffu, bm0, o));
            bm1 = fmaxf(bm1, __shfl_xor_sync(0xffffffffu, bm1, o));
        }
        float mn0 = fmaxf(m0, bm0);
        float mn1 = fmaxf(m1, bm1);

        float p0[4], p1[4], bs0 = 0.0f, bs1 = 0.0f;
        #pragma unroll
        for (int c = 0; c < 4; c++) {
            p0[c] = expf(s0[c] - mn0); bs0 += p0[c];
            p1[c] = expf(s1[c] - mn1); bs1 += p1[c];
        }
        #pragma unroll
        for (int o = 1; o < 8; o <<= 1) {
            bs0 += __shfl_xor_sync(0xffffffffu, bs0, o);
            bs1 += __shfl_xor_sync(0xffffffffu, bs1, o);
        }
        float a0 = expf(m0 - mn0);
        float a1 = expf(m1 - mn1);
        l0 = l0 * a0 + bs0;
        l1 = l1 * a1 + bs1;
        m0 = mn0; m1 = mn1;

        __syncthreads();  // all threads done reading K tile

        // Load V tile into same buffer; publish P; rescale accumulators
        for (int idx = tid; idx < 32 * 128; idx += 256) {
            int r = idx >> 7, d = idx & 127;
            KVs[r * 129 + d] = g_v[((size_t)(b * Ts + kt * 32 + r) * Hkv + hk) * Dd + d];
        }
        #pragma unroll
        for (int c = 0; c < 4; c++) {
            Ps[r0 * 33 + jj + c] = p0[c];
            Ps[r1 * 33 + jj + c] = p1[c];
        }
        #pragma unroll
        for (int c = 0; c < 16; c++) { acc[0][c] *= a0; acc[1][c] *= a1; }
        __syncthreads();

        // O += P @ V  (2 rows x 16 strided cols per thread)
        #pragma unroll 4
        for (int j = 0; j < 32; j++) {
            float pp0 = Ps[r0 * 33 + j];
            float pp1 = Ps[r1 * 33 + j];
            #pragma unroll
            for (int c = 0; c < 16; c++) {
                float vv = KVs[j * 129 + j4 + 8 * c];
                acc[0][c] += pp0 * vv;
                acc[1][c] += pp1 * vv;
            }
        }
    }

    // Epilogue: normalize and store
    float inv0 = 1.0f / l0;
    float inv1 = 1.0f / l1;
    #pragma unroll
    for (int c = 0; c < 16; c++) {
        int d = j4 + 8 * c;
        g_o[((size_t)(b * Ts + qBase + r0) * Hq + h) * Dd + d] = acc[0][c] * inv0;
        g_o[((size_t)(b * Ts + qBase + r1) * Hq + h) * Dd + d] = acc[1][c] * inv1;
    }
}

// ---------------------------------------------------------------------------
// Launch
// ---------------------------------------------------------------------------
extern "C" void kernel_launch(void* const* d_in, const int* in_sizes, int n_in,
                              void* d_out, int out_size)
{
    const float* stm  = (const float*)d_in[0];
    const float* wq   = (const float*)d_in[1];
    const float* wk   = (const float*)d_in[2];
    const float* wv   = (const float*)d_in[3];
    const float* wo   = (const float*)d_in[4];
    const float* cosv = (const float*)d_in[5];
    const float* sinv = (const float*)d_in[6];
    // d_in[7], d_in[8]: mask_w / mask_b — causal mask applied analytically.
    float* out = (float*)d_out;

    float *q, *k, *v, *o;
    cudaGetSymbolAddress((void**)&q, g_q);
    cudaGetSymbolAddress((void**)&k, g_k);
    cudaGetSymbolAddress((void**)&v, g_v);
    cudaGetSymbolAddress((void**)&o, g_o);

    cudaFuncSetAttribute(attn_kernel, cudaFuncAttributeMaxDynamicSharedMemorySize,
                         ATTN_SMEM);

    // QKV projections
    sgemm_kernel<<<dim3(INNER / GBN, INNER / GBM), 256>>>(stm, wq, q, INNER, INNER, INNER);
    sgemm_kernel<<<dim3(KVIN  / GBN, INNER / GBM), 256>>>(stm, wk, k, INNER, KVIN,  INNER);
    sgemm_kernel<<<dim3(KVIN  / GBN, INNER / GBM), 256>>>(stm, wv, v, INNER, KVIN,  INNER);

    // RoPE on q and k
    {
        int nq = Bb * Ts * Hq  * 64;
        int nk = Bb * Ts * Hkv * 64;
        rope_kernel<<<(nq + 255) / 256, 256>>>(q, cosv, sinv, Hq,  nq);
        rope_kernel<<<(nk + 255) / 256, 256>>>(k, cosv, sinv, Hkv, nk);
    }

    // Attention
    attn_kernel<<<dim3(Ts / 64, Hq, Bb), 256, ATTN_SMEM>>>();

    // Output projection
    sgemm_kernel<<<dim3(INNER / GBN, INNER / GBM), 256>>>(o, wo, out, INNER, INNER, INNER);
}

// round 3
// speedup vs baseline: 1.8597x; 1.8597x over previous
#include <cuda_runtime.h>
#include <cuda_bf16.h>
#include <math.h>
#include <stdint.h>

// Problem constants
#define Bb    2
#define Ts    2048
#define Hq    32
#define Hkv   8
#define Dd    128
#define INNER 4096
#define KVIN  1024
#define MTOT  4096              // B*T
#define ATTN_SCALE 0.08838834764831845f

// ---------------------------------------------------------------------------
// Scratch (device globals)
// ---------------------------------------------------------------------------
__device__ float g_q[Bb*Ts*Hq*Dd];
__device__ float g_k[Bb*Ts*Hkv*Dd];
__device__ float g_v[Bb*Ts*Hkv*Dd];
__device__ float g_o[Bb*Ts*Hq*Dd];

// bf16 split-precision operands (raw u16)
__device__ unsigned short g_xh [MTOT*INNER],  g_xl [MTOT*INNER];
__device__ unsigned short g_wqh[INNER*INNER], g_wql[INNER*INNER];
__device__ unsigned short g_wkh[KVIN*INNER],  g_wkl[KVIN*INNER];
__device__ unsigned short g_wvh[KVIN*INNER],  g_wvl[KVIN*INNER];
__device__ unsigned short g_woh[INNER*INNER], g_wol[INNER*INNER];
__device__ unsigned short g_oh [MTOT*INNER],  g_ol [MTOT*INNER];

// ---------------------------------------------------------------------------
// Helpers
// ---------------------------------------------------------------------------
__device__ __forceinline__ uint32_t smem_u32(const void* p) {
    uint32_t a;
    asm("{ .reg .u64 t; cvta.to.shared.u64 t, %1; cvt.u32.u64 %0, t; }"
        : "=r"(a) : "l"(p));
    return a;
}
#define CPA16(d,s) asm volatile("cp.async.cg.shared.global [%0], [%1], 16;" :: "r"(d), "l"(s))
#define CPC()      asm volatile("cp.async.commit_group;" ::: "memory")
#define CPW(n)     asm volatile("cp.async.wait_group %0;" :: "n"(n) : "memory")

__device__ __forceinline__ void ldsm4(uint32_t* r, uint32_t a) {
    asm volatile("ldmatrix.sync.aligned.m8n8.x4.shared.b16 {%0,%1,%2,%3}, [%4];"
        : "=r"(r[0]), "=r"(r[1]), "=r"(r[2]), "=r"(r[3]) : "r"(a));
}
__device__ __forceinline__ void mma16816(float* c, const uint32_t* a, const uint32_t* b) {
    asm volatile("mma.sync.aligned.m16n8k16.row.col.f32.bf16.bf16.f32 "
        "{%0,%1,%2,%3}, {%4,%5,%6,%7}, {%8,%9}, {%0,%1,%2,%3};"
        : "+f"(c[0]), "+f"(c[1]), "+f"(c[2]), "+f"(c[3])
        : "r"(a[0]), "r"(a[1]), "r"(a[2]), "r"(a[3]), "r"(b[0]), "r"(b[1]));
}

__device__ __forceinline__ unsigned short f2bf(float x) {
    __nv_bfloat16 h = __float2bfloat16(x);
    return *reinterpret_cast<unsigned short*>(&h);
}
__device__ __forceinline__ float bf2f(unsigned short u) {
    __nv_bfloat16 h = *reinterpret_cast<__nv_bfloat16*>(&u);
    return __bfloat162float(h);
}

// ---------------------------------------------------------------------------
// Conversion kernels
// ---------------------------------------------------------------------------
__global__ void split_kernel(const float* __restrict__ x,
                             unsigned short* __restrict__ h,
                             unsigned short* __restrict__ l, int n)
{
    int i = (blockIdx.x * 256 + threadIdx.x) * 4;
    if (i >= n) return;
    float4 v = *(const float4*)(x + i);
    unsigned short h0 = f2bf(v.x), h1 = f2bf(v.y), h2 = f2bf(v.z), h3 = f2bf(v.w);
    ushort4 hh; hh.x = h0; hh.y = h1; hh.z = h2; hh.w = h3;
    *(ushort4*)(h + i) = hh;
    ushort4 ll;
    ll.x = f2bf(v.x - bf2f(h0)); ll.y = f2bf(v.y - bf2f(h1));
    ll.z = f2bf(v.z - bf2f(h2)); ll.w = f2bf(v.w - bf2f(h3));
    *(ushort4*)(l + i) = ll;
}

// w[K,N] -> out[N,K] (transpose) + hi/lo split
__global__ void transpose_split(const float* __restrict__ w,
                                unsigned short* __restrict__ th,
                                unsigned short* __restrict__ tl, int K, int N)
{
    __shared__ float t[32][33];
    int n0 = blockIdx.x * 32, k0 = blockIdx.y * 32;
    #pragma unroll
    for (int i = 0; i < 32; i += 8)
        t[threadIdx.y + i][threadIdx.x] =
            w[(size_t)(k0 + threadIdx.y + i) * N + n0 + threadIdx.x];
    __syncthreads();
    #pragma unroll
    for (int i = 0; i < 32; i += 8) {
        float x = t[threadIdx.x][threadIdx.y + i];
        size_t o = (size_t)(n0 + threadIdx.y + i) * K + k0 + threadIdx.x;
        unsigned short hb = f2bf(x);
        th[o] = hb;
        tl[o] = f2bf(x - bf2f(hb));
    }
}

// ---------------------------------------------------------------------------
// mma.sync split-bf16 GEMM: C[M,N] = A[M,K] @ Bt[N,K]^T  (3-term split)
// CTA 128x128, 8 warps (warp tile 64m x 32n), K chunk 32, 4-stage cp.async.
// smem per stage: Ah 8K | Al 8K | Bh 8K | Bl 8K = 32KB. XOR swizzle on 16B
// chunks: off = row*64 + ((c ^ ((row>>1)&3))<<4) — conflict-free for both
// cp.async stores and ldmatrix reads.
// ---------------------------------------------------------------------------
#define NSTG  4
#define STGB  32768
#define GSMEM (NSTG*STGB)

__global__ __launch_bounds__(256, 1) void gemm_mma(
    const unsigned short* __restrict__ Ah, const unsigned short* __restrict__ Al,
    const unsigned short* __restrict__ Bh, const unsigned short* __restrict__ Bl,
    float* __restrict__ C, int N, int K)
{
    extern __shared__ char smraw[];
    const uint32_t sb = smem_u32(smraw);
    const int tid  = threadIdx.x;
    const int wid  = tid >> 5;
    const int lane = tid & 31;
    const int mBase = blockIdx.y * 128;
    const int nBase = blockIdx.x * 128;
    const int warp_m = (wid & 1) * 64;
    const int warp_n = (wid >> 1) * 32;

    // ldmatrix lane addresses (stage 0, k-step 0); s toggles addr bit5 (XOR 32)
    uint32_t aAddr[4], bAddr[2];
    {
        int r    = lane & 15;
        int half = lane >> 4;
        #pragma unroll
        for (int mt = 0; mt < 4; mt++) {
            int row = warp_m + mt * 16 + r;
            int sw  = (row >> 1) & 3;
            aAddr[mt] = sb + row * 64 + ((half ^ sw) << 4);
        }
        int nIn = (lane & 7) + (lane >> 4) * 8;
        int cl  = (lane >> 3) & 1;
        #pragma unroll
        for (int bt = 0; bt < 2; bt++) {
            int row = warp_n + bt * 16 + nIn;
            int sw  = (row >> 1) & 3;
            bAddr[bt] = sb + 16384 + row * 64 + ((cl ^ sw) << 4);
        }
    }

    const int ldRow = tid >> 2;   // 0..63 (two halves: +0, +64)
    const int ldC   = tid & 3;

    float cacc[4][4][4];
    #pragma unroll
    for (int a = 0; a < 4; a++)
        #pragma unroll
        for (int b = 0; b < 4; b++)
            #pragma unroll
            for (int c = 0; c < 4; c++) cacc[a][b][c] = 0.0f;

    const int NCH = K >> 5;

    auto load_chunk = [&](int st, int k0) {
        #pragma unroll
        for (int h = 0; h < 2; h++) {
            int row = ldRow + h * 64;
            int sw  = (row >> 1) & 3;
            uint32_t so = sb + st * STGB + row * 64 + ((ldC ^ sw) << 4);
            size_t ga = (size_t)(mBase + row) * K + k0 + ldC * 8;
            CPA16(so,         Ah + ga);
            CPA16(so + 8192,  Al + ga);
            size_t gb = (size_t)(nBase + row) * K + k0 + ldC * 8;
            CPA16(so + 16384, Bh + gb);
            CPA16(so + 24576, Bl + gb);
        }
        CPC();
    };

    load_chunk(0, 0);
    load_chunk(1, 32);
    load_chunk(2, 64);

    for (int i = 0; i < NCH; i++) {
        CPW(2);
        __syncthreads();
        uint32_t stOff = (uint32_t)(i & 3) * STGB;

        #pragma unroll
        for (int s = 0; s < 2; s++) {
            uint32_t sx = (uint32_t)(s << 5);  // XOR mask for k-step
            uint32_t a_hi[4][4], a_lo[4][4], b_hi[2][4], b_lo[2][4];
            #pragma unroll
            for (int mt = 0; mt < 4; mt++) {
                uint32_t ad = (aAddr[mt] ^ sx) + stOff;
                ldsm4(a_hi[mt], ad);
                ldsm4(a_lo[mt], ad + 8192);
            }
            #pragma unroll
            for (int bt = 0; bt < 2; bt++) {
                uint32_t bd = (bAddr[bt] ^ sx) + stOff;
                ldsm4(b_hi[bt], bd);
                ldsm4(b_lo[bt], bd + 8192);
            }
            #pragma unroll
            for (int mt = 0; mt < 4; mt++) {
                #pragma unroll
                for (int bt = 0; bt < 2; bt++) {
                    mma16816(cacc[mt][bt*2],   a_hi[mt], &b_hi[bt][0]);
                    mma16816(cacc[mt][bt*2+1], a_hi[mt], &b_hi[bt][2]);
                    mma16816(cacc[mt][bt*2],   a_hi[mt], &b_lo[bt][0]);
                    mma16816(cacc[mt][bt*2+1], a_hi[mt], &b_lo[bt][2]);
                    mma16816(cacc[mt][bt*2],   a_lo[mt], &b_hi[bt][0]);
                    mma16816(cacc[mt][bt*2+1], a_lo[mt], &b_hi[bt][2]);
                }
            }
        }
        __syncthreads();
        int nx = i + 3;
        if (nx < NCH) load_chunk(nx & 3, nx << 5);
        else          CPC();
    }

    // Epilogue: fp32 accumulators -> C
    const int rBase = mBase + warp_m + (lane >> 2);
    const int cBase = nBase + warp_n + (lane & 3) * 2;
    #pragma unroll
    for (int mt = 0; mt < 4; mt++) {
        #pragma unroll
        for (int nt = 0; nt < 4; nt++) {
            int r0 = rBase + mt * 16;
            int c0 = cBase + nt * 8;
            float2 v0 = make_float2(cacc[mt][nt][0], cacc[mt][nt][1]);
            float2 v1 = make_float2(cacc[mt][nt][2], cacc[mt][nt][3]);
            *(float2*)&C[(size_t)r0 * N + c0]       = v0;
            *(float2*)&C[(size_t)(r0 + 8) * N + c0] = v1;
        }
    }
}

// ---------------------------------------------------------------------------
// RoPE (rotate-half), in-place
// ---------------------------------------------------------------------------
__global__ void rope_kernel(float* __restrict__ buf,
                            const float* __restrict__ cs,
                            const float* __restrict__ sn,
                            int HH, int nPairs)
{
    int idx = blockIdx.x * blockDim.x + threadIdx.x;
    if (idx >= nPairs) return;
    int d    = idx & 63;
    int rest = idx >> 6;
    int t    = (rest / HH) % Ts;
    size_t base = (size_t)rest * 128;
    float l = buf[base + d];
    float r = buf[base + d + 64];
    float c0 = cs[t * 128 + d],      s0 = sn[t * 128 + d];
    float c1 = cs[t * 128 + d + 64], s1 = sn[t * 128 + d + 64];
    buf[base + d]      = l * c0 - r * s0;
    buf[base + d + 64] = r * c1 + l * s1;
}

// ---------------------------------------------------------------------------
// Flash-style causal GQA attention, fp32
// ---------------------------------------------------------------------------
#define ATTN_SMEM ((64*130 + 32*129 + 64*33) * 4)

__global__ __launch_bounds__(256) void attn_kernel()
{
    extern __shared__ float sm[];
    float* Qs  = sm;
    float* KVs = Qs + 64 * 130;
    float* Ps  = KVs + 32 * 129;

    const int tid   = threadIdx.x;
    const int qb    = blockIdx.x;
    const int h     = blockIdx.y;
    const int b     = blockIdx.z;
    const int qBase = qb * 64;
    const int hk    = h >> 2;
    const int r0    = tid >> 3;
    const int r1    = r0 + 32;
    const int j4    = tid & 7;
    const int jj    = j4 * 4;

    for (int idx = tid; idx < 64 * 128; idx += 256) {
        int r = idx >> 7, d = idx & 127;
        Qs[r * 130 + d] = g_q[((size_t)(b * Ts + qBase + r) * Hq + h) * Dd + d];
    }

    float acc[2][16];
    #pragma unroll
    for (int c = 0; c < 16; c++) { acc[0][c] = 0.0f; acc[1][c] = 0.0f; }
    float m0 = -INFINITY, m1 = -INFINITY, l0 = 0.0f, l1 = 0.0f;

    const int nTiles = qb * 2 + 2;
    for (int kt = 0; kt < nTiles; kt++) {
        __syncthreads();
        for (int idx = tid; idx < 32 * 128; idx += 256) {
            int r = idx >> 7, d = idx & 127;
            KVs[r * 129 + d] = g_k[((size_t)(b * Ts + kt * 32 + r) * Hkv + hk) * Dd + d];
        }
        __syncthreads();

        float s0[4] = {0,0,0,0}, s1[4] = {0,0,0,0};
        #pragma unroll 4
        for (int d = 0; d < 128; d++) {
            float q0 = Qs[r0 * 130 + d];
            float q1 = Qs[r1 * 130 + d];
            #pragma unroll
            for (int c = 0; c < 4; c++) {
                float kv = KVs[(jj + c) * 129 + d];
                s0[c] += q0 * kv;
                s1[c] += q1 * kv;
            }
        }

        #pragma unroll
        for (int c = 0; c < 4; c++) {
            int jg = kt * 32 + jj + c;
            s0[c] = (jg <= qBase + r0) ? s0[c] * ATTN_SCALE : -30000.0f;
            s1[c] = (jg <= qBase + r1) ? s1[c] * ATTN_SCALE : -30000.0f;
        }

        float bm0 = fmaxf(fmaxf(s0[0], s0[1]), fmaxf(s0[2], s0[3]));
        float bm1 = fmaxf(fmaxf(s1[0], s1[1]), fmaxf(s1[2], s1[3]));
        #pragma unroll
        for (int o = 1; o < 8; o <<= 1) {
            bm0 = fmaxf(bm0, __shfl_xor_sync(0xffffffffu, bm0, o));
            bm1 = fmaxf(bm1, __shfl_xor_sync(0xffffffffu, bm1, o));
        }
        float mn0 = fmaxf(m0, bm0);
        float mn1 = fmaxf(m1, bm1);

        float p0[4], p1[4], bs0 = 0.0f, bs1 = 0.0f;
        #pragma unroll
        for (int c = 0; c < 4; c++) {
            p0[c] = expf(s0[c] - mn0); bs0 += p0[c];
            p1[c] = expf(s1[c] - mn1); bs1 += p1[c];
        }
        #pragma unroll
        for (int o = 1; o < 8; o <<= 1) {
            bs0 += __shfl_xor_sync(0xffffffffu, bs0, o);
            bs1 += __shfl_xor_sync(0xffffffffu, bs1, o);
        }
        float a0 = expf(m0 - mn0);
        float a1 = expf(m1 - mn1);
        l0 = l0 * a0 + bs0;
        l1 = l1 * a1 + bs1;
        m0 = mn0; m1 = mn1;

        __syncthreads();

        for (int idx = tid; idx < 32 * 128; idx += 256) {
            int r = idx >> 7, d = idx & 127;
            KVs[r * 129 + d] = g_v[((size_t)(b * Ts + kt * 32 + r) * Hkv + hk) * Dd + d];
        }
        #pragma unroll
        for (int c = 0; c < 4; c++) {
            Ps[r0 * 33 + jj + c] = p0[c];
            Ps[r1 * 33 + jj + c] = p1[c];
        }
        #pragma unroll
        for (int c = 0; c < 16; c++) { acc[0][c] *= a0; acc[1][c] *= a1; }
        __syncthreads();

        #pragma unroll 4
        for (int j = 0; j < 32; j++) {
            float pp0 = Ps[r0 * 33 + j];
            float pp1 = Ps[r1 * 33 + j];
            #pragma unroll
            for (int c = 0; c < 16; c++) {
                float vv = KVs[j * 129 + j4 + 8 * c];
                acc[0][c] += pp0 * vv;
                acc[1][c] += pp1 * vv;
            }
        }
    }

    float inv0 = 1.0f / l0;
    float inv1 = 1.0f / l1;
    #pragma unroll
    for (int c = 0; c < 16; c++) {
        int d = j4 + 8 * c;
        g_o[((size_t)(b * Ts + qBase + r0) * Hq + h) * Dd + d] = acc[0][c] * inv0;
        g_o[((size_t)(b * Ts + qBase + r1) * Hq + h) * Dd + d] = acc[1][c] * inv1;
    }
}

// ---------------------------------------------------------------------------
// Launch
// ---------------------------------------------------------------------------
extern "C" void kernel_launch(void* const* d_in, const int* in_sizes, int n_in,
                              void* d_out, int out_size)
{
    const float* stm  = (const float*)d_in[0];
    const float* wq   = (const float*)d_in[1];
    const float* wk   = (const float*)d_in[2];
    const float* wv   = (const float*)d_in[3];
    const float* wo   = (const float*)d_in[4];
    const float* cosv = (const float*)d_in[5];
    const float* sinv = (const float*)d_in[6];
    float* out = (float*)d_out;

    float *q, *k, *v, *o;
    cudaGetSymbolAddress((void**)&q, g_q);
    cudaGetSymbolAddress((void**)&k, g_k);
    cudaGetSymbolAddress((void**)&v, g_v);
    cudaGetSymbolAddress((void**)&o, g_o);
    unsigned short *xh, *xl, *wqh, *wql, *wkh, *wkl, *wvh, *wvl, *woh, *wol, *oh, *ol;
    cudaGetSymbolAddress((void**)&xh,  g_xh);  cudaGetSymbolAddress((void**)&xl,  g_xl);
    cudaGetSymbolAddress((void**)&wqh, g_wqh); cudaGetSymbolAddress((void**)&wql, g_wql);
    cudaGetSymbolAddress((void**)&wkh, g_wkh); cudaGetSymbolAddress((void**)&wkl, g_wkl);
    cudaGetSymbolAddress((void**)&wvh, g_wvh); cudaGetSymbolAddress((void**)&wvl, g_wvl);
    cudaGetSymbolAddress((void**)&woh, g_woh); cudaGetSymbolAddress((void**)&wol, g_wol);
    cudaGetSymbolAddress((void**)&oh,  g_oh);  cudaGetSymbolAddress((void**)&ol,  g_ol);

    cudaFuncSetAttribute(attn_kernel, cudaFuncAttributeMaxDynamicSharedMemorySize,
                         ATTN_SMEM);
    cudaFuncSetAttribute(gemm_mma, cudaFuncAttributeMaxDynamicSharedMemorySize,
                         GSMEM);

    // Conversions
    split_kernel<<<MTOT*INNER/1024, 256>>>(stm, xh, xl, MTOT*INNER);
    transpose_split<<<dim3(INNER/32, INNER/32), dim3(32,8)>>>(wq, wqh, wql, INNER, INNER);
    transpose_split<<<dim3(KVIN/32,  INNER/32), dim3(32,8)>>>(wk, wkh, wkl, INNER, KVIN);
    transpose_split<<<dim3(KVIN/32,  INNER/32), dim3(32,8)>>>(wv, wvh, wvl, INNER, KVIN);
    transpose_split<<<dim3(INNER/32, INNER/32), dim3(32,8)>>>(wo, woh, wol, INNER, INNER);

    // QKV projections (tensor-core split-bf16)
    gemm_mma<<<dim3(INNER/128, MTOT/128), 256, GSMEM>>>(xh, xl, wqh, wql, q, INNER, INNER);
    gemm_mma<<<dim3(KVIN/128,  MTOT/128), 256, GSMEM>>>(xh, xl, wkh, wkl, k, KVIN,  INNER);
    gemm_mma<<<dim3(KVIN/128,  MTOT/128), 256, GSMEM>>>(xh, xl, wvh, wvl, v, KVIN,  INNER);

    // RoPE
    {
        int nq = Bb * Ts * Hq  * 64;
        int nk = Bb * Ts * Hkv * 64;
        rope_kernel<<<(nq + 255) / 256, 256>>>(q, cosv, sinv, Hq,  nq);
        rope_kernel<<<(nk + 255) / 256, 256>>>(k, cosv, sinv, Hkv, nk);
    }

    // Attention (fp32 SIMT)
    attn_kernel<<<dim3(Ts / 64, Hq, Bb), 256, ATTN_SMEM>>>();

    // Output projection
    split_kernel<<<MTOT*INNER/1024, 256>>>(o, oh, ol, MTOT*INNER);
    gemm_mma<<<dim3(INNER/128, MTOT/128), 256, GSMEM>>>(oh, ol, woh, wol, out, INNER, INNER);
}

// round 4
// speedup vs baseline: 3.1846x; 1.7124x over previous
#include <cuda_runtime.h>
#include <cuda_bf16.h>
#include <math.h>
#include <stdint.h>

// Problem constants
#define Bb    2
#define Ts    2048
#define Hq    32
#define Hkv   8
#define Dd    128
#define INNER 4096
#define KVIN  1024
#define MTOT  4096              // B*T
#define ATTN_SCALE 0.08838834764831845f

// ---------------------------------------------------------------------------
// Scratch (device globals)
// ---------------------------------------------------------------------------
__device__ float g_q[Bb*Ts*Hq*Dd];
__device__ float g_k[Bb*Ts*Hkv*Dd];
__device__ float g_v[Bb*Ts*Hkv*Dd];

// bf16 split-precision operands (raw u16)
__device__ unsigned short g_xh [MTOT*INNER],  g_xl [MTOT*INNER];
__device__ unsigned short g_wqh[INNER*INNER], g_wql[INNER*INNER];
__device__ unsigned short g_wkh[KVIN*INNER],  g_wkl[KVIN*INNER];
__device__ unsigned short g_wvh[KVIN*INNER],  g_wvl[KVIN*INNER];
__device__ unsigned short g_woh[INNER*INNER], g_wol[INNER*INNER];
__device__ unsigned short g_oh [MTOT*INNER],  g_ol [MTOT*INNER];

// attention operands
__device__ unsigned short g_qh2[Bb*Hq*Ts*Dd],  g_ql2[Bb*Hq*Ts*Dd];    // [b,h,t,d]
__device__ unsigned short g_kh2[Bb*Hkv*Ts*Dd], g_kl2[Bb*Hkv*Ts*Dd];   // [b,hkv,t,d]
__device__ unsigned short g_vth[Bb*Hkv*Ts*Dd], g_vtl[Bb*Hkv*Ts*Dd];   // [b,hkv,d,t]

// ---------------------------------------------------------------------------
// Helpers
// ---------------------------------------------------------------------------
__device__ __forceinline__ uint32_t smem_u32(const void* p) {
    uint32_t a;
    asm("{ .reg .u64 t; cvta.to.shared.u64 t, %1; cvt.u32.u64 %0, t; }"
        : "=r"(a) : "l"(p));
    return a;
}
#define CPA16(d,s) asm volatile("cp.async.cg.shared.global [%0], [%1], 16;" :: "r"(d), "l"(s))
#define CPC()      asm volatile("cp.async.commit_group;" ::: "memory")
#define CPW(n)     asm volatile("cp.async.wait_group %0;" :: "n"(n) : "memory")

__device__ __forceinline__ void ldsm4(uint32_t* r, uint32_t a) {
    asm volatile("ldmatrix.sync.aligned.m8n8.x4.shared.b16 {%0,%1,%2,%3}, [%4];"
        : "=r"(r[0]), "=r"(r[1]), "=r"(r[2]), "=r"(r[3]) : "r"(a));
}
__device__ __forceinline__ void mma16816(float* c, const uint32_t* a, const uint32_t* b) {
    asm volatile("mma.sync.aligned.m16n8k16.row.col.f32.bf16.bf16.f32 "
        "{%0,%1,%2,%3}, {%4,%5,%6,%7}, {%8,%9}, {%0,%1,%2,%3};"
        : "+f"(c[0]), "+f"(c[1]), "+f"(c[2]), "+f"(c[3])
        : "r"(a[0]), "r"(a[1]), "r"(a[2]), "r"(a[3]), "r"(b[0]), "r"(b[1]));
}

__device__ __forceinline__ unsigned short f2bf(float x) {
    __nv_bfloat16 h = __float2bfloat16(x);
    return *reinterpret_cast<unsigned short*>(&h);
}
__device__ __forceinline__ float bf2f(unsigned short u) {
    __nv_bfloat16 h = *reinterpret_cast<__nv_bfloat16*>(&u);
    return __bfloat162float(h);
}
__device__ __forceinline__ uint32_t pk2(float a, float b) {
    return (uint32_t)f2bf(a) | ((uint32_t)f2bf(b) << 16);
}
__device__ __forceinline__ uint32_t pk2lo(float a, float b) {
    return pk2(a - bf2f(f2bf(a)), b - bf2f(f2bf(b)));
}

// ---------------------------------------------------------------------------
// Conversion kernels
// ---------------------------------------------------------------------------
__global__ void split_kernel(const float* __restrict__ x,
                             unsigned short* __restrict__ h,
                             unsigned short* __restrict__ l, int n)
{
    int i = (blockIdx.x * 256 + threadIdx.x) * 4;
    if (i >= n) return;
    float4 v = *(const float4*)(x + i);
    unsigned short h0 = f2bf(v.x), h1 = f2bf(v.y), h2 = f2bf(v.z), h3 = f2bf(v.w);
    ushort4 hh; hh.x = h0; hh.y = h1; hh.z = h2; hh.w = h3;
    *(ushort4*)(h + i) = hh;
    ushort4 ll;
    ll.x = f2bf(v.x - bf2f(h0)); ll.y = f2bf(v.y - bf2f(h1));
    ll.z = f2bf(v.z - bf2f(h2)); ll.w = f2bf(v.w - bf2f(h3));
    *(ushort4*)(l + i) = ll;
}

// w[K,N] -> out[N,K] (transpose) + hi/lo split
__global__ void transpose_split(const float* __restrict__ w,
                                unsigned short* __restrict__ th,
                                unsigned short* __restrict__ tl, int K, int N)
{
    __shared__ float t[32][33];
    int n0 = blockIdx.x * 32, k0 = blockIdx.y * 32;
    #pragma unroll
    for (int i = 0; i < 32; i += 8)
        t[threadIdx.y + i][threadIdx.x] =
            w[(size_t)(k0 + threadIdx.y + i) * N + n0 + threadIdx.x];
    __syncthreads();
    #pragma unroll
    for (int i = 0; i < 32; i += 8) {
        float x = t[threadIdx.x][threadIdx.y + i];
        size_t o = (size_t)(n0 + threadIdx.y + i) * K + k0 + threadIdx.x;
        unsigned short hb = f2bf(x);
        th[o] = hb;
        tl[o] = f2bf(x - bf2f(hb));
    }
}

// (b,t,HH,d) fp32 -> (b,HH,t,d) bf16 hi/lo
__global__ void relayout_split(const float* __restrict__ src,
                               unsigned short* __restrict__ dh,
                               unsigned short* __restrict__ dl, int HH, int n4)
{
    int idx = blockIdx.x * 256 + threadIdx.x;
    if (idx >= n4) return;
    size_t i4 = (size_t)idx * 4;
    int d = (int)(i4 & 127);
    size_t rest = i4 >> 7;
    int hh = (int)(rest % HH);
    size_t bt = rest / HH;
    int t = (int)(bt % Ts);
    int b = (int)(bt / Ts);
    float4 v = *(const float4*)(src + i4);
    size_t o = (((size_t)(b * HH + hh) * Ts + t) << 7) + d;
    unsigned short h0 = f2bf(v.x), h1 = f2bf(v.y), h2 = f2bf(v.z), h3 = f2bf(v.w);
    ushort4 hh4; hh4.x = h0; hh4.y = h1; hh4.z = h2; hh4.w = h3;
    *(ushort4*)(dh + o) = hh4;
    ushort4 ll;
    ll.x = f2bf(v.x - bf2f(h0)); ll.y = f2bf(v.y - bf2f(h1));
    ll.z = f2bf(v.z - bf2f(h2)); ll.w = f2bf(v.w - bf2f(h3));
    *(ushort4*)(dl + o) = ll;
}

// g_v (b,t,hkv,d) fp32 -> (b,hkv,d,t) bf16 hi/lo
__global__ void vtrans_split(const float* __restrict__ v,
                             unsigned short* __restrict__ th,
                             unsigned short* __restrict__ tl)
{
    __shared__ float s[32][33];
    int t0 = blockIdx.x * 32, d0 = blockIdx.y * 32;
    int b = blockIdx.z >> 3, hk = blockIdx.z & 7;
    int tx = threadIdx.x, ty = threadIdx.y;
    #pragma unroll
    for (int i = 0; i < 32; i += 8)
        s[ty + i][tx] = v[((size_t)(b * Ts + t0 + ty + i) * Hkv + hk) * Dd + d0 + tx];
    __syncthreads();
    #pragma unroll
    for (int i = 0; i < 32; i += 8) {
        float x = s[tx][ty + i];
        size_t o = ((size_t)((b * Hkv + hk) * Dd + d0 + ty + i)) * Ts + t0 + tx;
        unsigned short hb = f2bf(x);
        th[o] = hb;
        tl[o] = f2bf(x - bf2f(hb));
    }
}

// ---------------------------------------------------------------------------
// mma.sync split-bf16 GEMM (unchanged from round 3)
// ---------------------------------------------------------------------------
#define NSTG  4
#define STGB  32768
#define GSMEM (NSTG*STGB)

__global__ __launch_bounds__(256, 1) void gemm_mma(
    const unsigned short* __restrict__ Ah, const unsigned short* __restrict__ Al,
    const unsigned short* __restrict__ Bh, const unsigned short* __restrict__ Bl,
    float* __restrict__ C, int N, int K)
{
    extern __shared__ char smraw[];
    const uint32_t sb = smem_u32(smraw);
    const int tid  = threadIdx.x;
    const int wid  = tid >> 5;
    const int lane = tid & 31;
    const int mBase = blockIdx.y * 128;
    const int nBase = blockIdx.x * 128;
    const int warp_m = (wid & 1) * 64;
    const int warp_n = (wid >> 1) * 32;

    uint32_t aAddr[4], bAddr[2];
    {
        int r    = lane & 15;
        int half = lane >> 4;
        #pragma unroll
        for (int mt = 0; mt < 4; mt++) {
            int row = warp_m + mt * 16 + r;
            int sw  = (row >> 1) & 3;
            aAddr[mt] = sb + row * 64 + ((half ^ sw) << 4);
        }
        int nIn = (lane & 7) + (lane >> 4) * 8;
        int cl  = (lane >> 3) & 1;
        #pragma unroll
        for (int bt = 0; bt < 2; bt++) {
            int row = warp_n + bt * 16 + nIn;
            int sw  = (row >> 1) & 3;
            bAddr[bt] = sb + 16384 + row * 64 + ((cl ^ sw) << 4);
        }
    }

    const int ldRow = tid >> 2;
    const int ldC   = tid & 3;

    float cacc[4][4][4];
    #pragma unroll
    for (int a = 0; a < 4; a++)
        #pragma unroll
        for (int b = 0; b < 4; b++)
            #pragma unroll
            for (int c = 0; c < 4; c++) cacc[a][b][c] = 0.0f;

    const int NCH = K >> 5;

    auto load_chunk = [&](int st, int k0) {
        #pragma unroll
        for (int h = 0; h < 2; h++) {
            int row = ldRow + h * 64;
            int sw  = (row >> 1) & 3;
            uint32_t so = sb + st * STGB + row * 64 + ((ldC ^ sw) << 4);
            size_t ga = (size_t)(mBase + row) * K + k0 + ldC * 8;
            CPA16(so,         Ah + ga);
            CPA16(so + 8192,  Al + ga);
            size_t gb = (size_t)(nBase + row) * K + k0 + ldC * 8;
            CPA16(so + 16384, Bh + gb);
            CPA16(so + 24576, Bl + gb);
        }
        CPC();
    };

    load_chunk(0, 0);
    load_chunk(1, 32);
    load_chunk(2, 64);

    for (int i = 0; i < NCH; i++) {
        CPW(2);
        __syncthreads();
        uint32_t stOff = (uint32_t)(i & 3) * STGB;

        #pragma unroll
        for (int s = 0; s < 2; s++) {
            uint32_t sx = (uint32_t)(s << 5);
            uint32_t a_hi[4][4], a_lo[4][4], b_hi[2][4], b_lo[2][4];
            #pragma unroll
            for (int mt = 0; mt < 4; mt++) {
                uint32_t ad = (aAddr[mt] ^ sx) + stOff;
                ldsm4(a_hi[mt], ad);
                ldsm4(a_lo[mt], ad + 8192);
            }
            #pragma unroll
            for (int bt = 0; bt < 2; bt++) {
                uint32_t bd = (bAddr[bt] ^ sx) + stOff;
                ldsm4(b_hi[bt], bd);
                ldsm4(b_lo[bt], bd + 8192);
            }
            #pragma unroll
            for (int mt = 0; mt < 4; mt++) {
                #pragma unroll
                for (int bt = 0; bt < 2; bt++) {
                    mma16816(cacc[mt][bt*2],   a_hi[mt], &b_hi[bt][0]);
                    mma16816(cacc[mt][bt*2+1], a_hi[mt], &b_hi[bt][2]);
                    mma16816(cacc[mt][bt*2],   a_hi[mt], &b_lo[bt][0]);
                    mma16816(cacc[mt][bt*2+1], a_hi[mt], &b_lo[bt][2]);
                    mma16816(cacc[mt][bt*2],   a_lo[mt], &b_hi[bt][0]);
                    mma16816(cacc[mt][bt*2+1], a_lo[mt], &b_hi[bt][2]);
                }
            }
        }
        __syncthreads();
        int nx = i + 3;
        if (nx < NCH) load_chunk(nx & 3, nx << 5);
        else          CPC();
    }

    const int rBase = mBase + warp_m + (lane >> 2);
    const int cBase = nBase + warp_n + (lane & 3) * 2;
    #pragma unroll
    for (int mt = 0; mt < 4; mt++) {
        #pragma unroll
        for (int nt = 0; nt < 4; nt++) {
            int r0 = rBase + mt * 16;
            int c0 = cBase + nt * 8;
            float2 v0 = make_float2(cacc[mt][nt][0], cacc[mt][nt][1]);
            float2 v1 = make_float2(cacc[mt][nt][2], cacc[mt][nt][3]);
            *(float2*)&C[(size_t)r0 * N + c0]       = v0;
            *(float2*)&C[(size_t)(r0 + 8) * N + c0] = v1;
        }
    }
}

// ---------------------------------------------------------------------------
// RoPE (rotate-half), in-place
// ---------------------------------------------------------------------------
__global__ void rope_kernel(float* __restrict__ buf,
                            const float* __restrict__ cs,
                            const float* __restrict__ sn,
                            int HH, int nPairs)
{
    int idx = blockIdx.x * blockDim.x + threadIdx.x;
    if (idx >= nPairs) return;
    int d    = idx & 63;
    int rest = idx >> 6;
    int t    = (rest / HH) % Ts;
    size_t base = (size_t)rest * 128;
    float l = buf[base + d];
    float r = buf[base + d + 64];
    float c0 = cs[t * 128 + d],      s0 = sn[t * 128 + d];
    float c1 = cs[t * 128 + d + 64], s1 = sn[t * 128 + d + 64];
    buf[base + d]      = l * c0 - r * s0;
    buf[base + d + 64] = r * c1 + l * s1;
}

// ---------------------------------------------------------------------------
// Tensor-core flash attention, split-bf16 (3-term), causal GQA.
// CTA: (qb, h, b); BM=128 q rows, 8 warps (m16 each), key tile BN=64, D=128.
// smem: Qh 32K | Ql 32K | 2 stages x [Kh 16K | Kl 16K | Vh 16K | Vl 16K].
// Swizzle: 16B chunk c of row r stored at ((c ^ (r&7))<<4).
// ---------------------------------------------------------------------------
#define AT_SMEM 196608

__global__ __launch_bounds__(256, 1) void attn_mma(
    const unsigned short* __restrict__ qh, const unsigned short* __restrict__ ql,
    const unsigned short* __restrict__ kh, const unsigned short* __restrict__ kl,
    const unsigned short* __restrict__ vh, const unsigned short* __restrict__ vl,
    unsigned short* __restrict__ oh, unsigned short* __restrict__ ol)
{
    extern __shared__ char smraw[];
    const uint32_t sb = smem_u32(smraw);
    const uint32_t QHs = sb;
    const uint32_t STs = sb + 65536;

    const int tid = threadIdx.x, wid = tid >> 5, lane = tid & 31;
    const int qb = blockIdx.x, h = blockIdx.y, b = blockIdx.z;
    const int hk = h >> 2;
    const int qBase = qb * 128;
    const int nT = qb * 2 + 2;

    const unsigned short* Qhg = qh + ((size_t)(b * Hq + h) * Ts + qBase) * Dd;
    const unsigned short* Qlg = ql + ((size_t)(b * Hq + h) * Ts + qBase) * Dd;
    const unsigned short* Khg = kh + (size_t)(b * Hkv + hk) * Ts * Dd;
    const unsigned short* Klg = kl + (size_t)(b * Hkv + hk) * Ts * Dd;
    const unsigned short* Vhg = vh + (size_t)(b * Hkv + hk) * Dd * Ts;
    const unsigned short* Vlg = vl + (size_t)(b * Hkv + hk) * Dd * Ts;

    // Q load: 128 rows x 16 chunks x 2 arrays = 4096 chunks
    #pragma unroll
    for (int t = 0; t < 16; t++) {
        int idx = tid + t * 256;
        int arr = idx >> 11, rem = idx & 2047;
        int r = rem >> 4, c = rem & 15;
        uint32_t dst = QHs + arr * 32768 + r * 256 + ((c ^ (r & 7)) << 4);
        const unsigned short* s = (arr ? Qlg : Qhg) + (size_t)r * Dd + c * 8;
        CPA16(dst, s);
    }

    auto load_tile = [&](int st, int kt) {
        uint32_t base = STs + st * 65536;
        #pragma unroll
        for (int t = 0; t < 8; t++) {       // K: 64 rows x 16 chunks x 2
            int idx = tid + t * 256;
            int arr = idx >> 10, rem = idx & 1023;
            int r = rem >> 4, c = rem & 15;
            uint32_t dst = base + arr * 16384 + r * 256 + ((c ^ (r & 7)) << 4);
            const unsigned short* s = (arr ? Klg : Khg) +
                (size_t)(kt * 64 + r) * Dd + c * 8;
            CPA16(dst, s);
        }
        #pragma unroll
        for (int t = 0; t < 8; t++) {       // Vt: 128 rows x 8 chunks x 2
            int idx = tid + t * 256;
            int arr = idx >> 10, rem = idx & 1023;
            int r = rem >> 3, c = rem & 7;
            uint32_t dst = base + 32768 + arr * 16384 + r * 128 + ((c ^ (r & 7)) << 4);
            const unsigned short* s = (arr ? Vlg : Vhg) +
                (size_t)r * Ts + kt * 64 + c * 8;
            CPA16(dst, s);
        }
    };

    load_tile(0, 0);
    CPC();

    // lane-constant address pieces
    const int qrow = wid * 16 + (lane & 15);
    const uint32_t qpb = (uint32_t)(qrow * 256 + (((lane >> 4) ^ (qrow & 1)) << 4));
    const uint32_t qpx = (uint32_t)((qrow & 6) << 4);
    const int nIn = (lane & 7) + ((lane >> 4) << 3);
    const int cl  = (lane >> 3) & 1;

    float m0 = -INFINITY, m1 = -INFINITY, l0 = 0.0f, l1 = 0.0f;
    float O[16][4];
    #pragma unroll
    for (int i = 0; i < 16; i++)
        #pragma unroll
        for (int j = 0; j < 4; j++) O[i][j] = 0.0f;

    const int rA = qBase + wid * 16 + (lane >> 2);
    const int rB = rA + 8;

    for (int kt = 0; kt < nT; kt++) {
        if (kt + 1 < nT) { load_tile((kt + 1) & 1, kt + 1); CPC(); CPW(1); }
        else            { CPW(0); }
        __syncthreads();
        const uint32_t KB = STs + (kt & 1) * 65536;
        const uint32_t VB = KB + 32768;

        // --- S = Q @ K^T (split, 3 terms) ---
        float S[8][4];
        #pragma unroll
        for (int i = 0; i < 8; i++)
            #pragma unroll
            for (int j = 0; j < 4; j++) S[i][j] = 0.0f;

        #pragma unroll
        for (int ks = 0; ks < 8; ks++) {
            uint32_t qa = QHs + qpb + (((uint32_t)ks << 5) ^ qpx);
            uint32_t ah[4], al[4];
            ldsm4(ah, qa);
            ldsm4(al, qa + 32768);
            #pragma unroll
            for (int np = 0; np < 4; np++) {
                int krow = np * 16 + nIn;
                uint32_t ka = KB + krow * 256 + ((uint32_t)((cl ^ (krow & 1)) << 4))
                            + (((uint32_t)ks << 5) ^ ((uint32_t)(krow & 6) << 4));
                uint32_t bh[4], bl[4];
                ldsm4(bh, ka);
                ldsm4(bl, ka + 16384);
                mma16816(S[2*np],   ah, &bh[0]);
                mma16816(S[2*np+1], ah, &bh[2]);
                mma16816(S[2*np],   ah, &bl[0]);
                mma16816(S[2*np+1], ah, &bl[2]);
                mma16816(S[2*np],   al, &bh[0]);
                mma16816(S[2*np+1], al, &bh[2]);
            }
        }

        // --- scale + causal mask ---
        if (kt >= 2 * qb) {
            #pragma unroll
            for (int nt = 0; nt < 8; nt++) {
                int jg = kt * 64 + nt * 8 + (lane & 3) * 2;
                S[nt][0] = (jg     <= rA) ? S[nt][0] * ATTN_SCALE : -30000.0f;
                S[nt][1] = (jg + 1 <= rA) ? S[nt][1] * ATTN_SCALE : -30000.0f;
                S[nt][2] = (jg     <= rB) ? S[nt][2] * ATTN_SCALE : -30000.0f;
                S[nt][3] = (jg + 1 <= rB) ? S[nt][3] * ATTN_SCALE : -30000.0f;
            }
        } else {
            #pragma unroll
            for (int nt = 0; nt < 8; nt++) {
                S[nt][0] *= ATTN_SCALE; S[nt][1] *= ATTN_SCALE;
                S[nt][2] *= ATTN_SCALE; S[nt][3] *= ATTN_SCALE;
            }
        }

        // --- online softmax ---
        float bm0 = -INFINITY, bm1 = -INFINITY;
        #pragma unroll
        for (int nt = 0; nt < 8; nt++) {
            bm0 = fmaxf(bm0, fmaxf(S[nt][0], S[nt][1]));
            bm1 = fmaxf(bm1, fmaxf(S[nt][2], S[nt][3]));
        }
        bm0 = fmaxf(bm0, __shfl_xor_sync(0xffffffffu, bm0, 1));
        bm0 = fmaxf(bm0, __shfl_xor_sync(0xffffffffu, bm0, 2));
        bm1 = fmaxf(bm1, __shfl_xor_sync(0xffffffffu, bm1, 1));
        bm1 = fmaxf(bm1, __shfl_xor_sync(0xffffffffu, bm1, 2));
        float mn0 = fmaxf(m0, bm0);
        float mn1 = fmaxf(m1, bm1);

        float bs0 = 0.0f, bs1 = 0.0f;
        #pragma unroll
        for (int nt = 0; nt < 8; nt++) {
            S[nt][0] = __expf(S[nt][0] - mn0); bs0 += S[nt][0];
            S[nt][1] = __expf(S[nt][1] - mn0); bs0 += S[nt][1];
            S[nt][2] = __expf(S[nt][2] - mn1); bs1 += S[nt][2];
            S[nt][3] = __expf(S[nt][3] - mn1); bs1 += S[nt][3];
        }
        bs0 += __shfl_xor_sync(0xffffffffu, bs0, 1);
        bs0 += __shfl_xor_sync(0xffffffffu, bs0, 2);
        bs1 += __shfl_xor_sync(0xffffffffu, bs1, 1);
        bs1 += __shfl_xor_sync(0xffffffffu, bs1, 2);

        float a0 = __expf(m0 - mn0);
        float a1 = __expf(m1 - mn1);
        l0 = l0 * a0 + bs0;
        l1 = l1 * a1 + bs1;
        m0 = mn0; m1 = mn1;
        #pragma unroll
        for (int dt = 0; dt < 16; dt++) {
            O[dt][0] *= a0; O[dt][1] *= a0;
            O[dt][2] *= a1; O[dt][3] *= a1;
        }

        // --- O += P @ V (split, 3 terms) ---
        #pragma unroll
        for (int j = 0; j < 4; j++) {
            uint32_t pah[4], pal[4];
            pah[0] = pk2  (S[2*j][0],   S[2*j][1]);
            pah[1] = pk2  (S[2*j][2],   S[2*j][3]);
            pah[2] = pk2  (S[2*j+1][0], S[2*j+1][1]);
            pah[3] = pk2  (S[2*j+1][2], S[2*j+1][3]);
            pal[0] = pk2lo(S[2*j][0],   S[2*j][1]);
            pal[1] = pk2lo(S[2*j][2],   S[2*j][3]);
            pal[2] = pk2lo(S[2*j+1][0], S[2*j+1][1]);
            pal[3] = pk2lo(S[2*j+1][2], S[2*j+1][3]);
            #pragma unroll
            for (int dp = 0; dp < 8; dp++) {
                int vrow = dp * 16 + nIn;
                uint32_t va = VB + vrow * 128 + ((uint32_t)((cl ^ (vrow & 1)) << 4))
                            + (((uint32_t)j << 5) ^ ((uint32_t)(vrow & 6) << 4));
                uint32_t bh[4], bl[4];
                ldsm4(bh, va);
                ldsm4(bl, va + 16384);
                mma16816(O[2*dp],   pah, &bh[0]);
                mma16816(O[2*dp+1], pah, &bh[2]);
                mma16816(O[2*dp],   pah, &bl[0]);
                mma16816(O[2*dp+1], pah, &bl[2]);
                mma16816(O[2*dp],   pal, &bh[0]);
                mma16816(O[2*dp+1], pal, &bh[2]);
            }
        }
        __syncthreads();
    }

    // --- epilogue: normalize, split to bf16 hi/lo, store (b,t,h,d) ---
    float inv0 = 1.0f / l0;
    float inv1 = 1.0f / l1;
    size_t rowA = ((size_t)(b * Ts + rA)) * INNER + h * Dd;
    size_t rowB = ((size_t)(b * Ts + rB)) * INNER + h * Dd;
    #pragma unroll
    for (int dt = 0; dt < 16; dt++) {
        int col = dt * 8 + (lane & 3) * 2;
        float x0 = O[dt][0] * inv0, x1 = O[dt][1] * inv0;
        float y0 = O[dt][2] * inv1, y1 = O[dt][3] * inv1;
        *(uint32_t*)&oh[rowA + col] = pk2(x0, x1);
        *(uint32_t*)&ol[rowA + col] = pk2lo(x0, x1);
        *(uint32_t*)&oh[rowB + col] = pk2(y0, y1);
        *(uint32_t*)&ol[rowB + col] = pk2lo(y0, y1);
    }
}

// ---------------------------------------------------------------------------
// Launch
// ---------------------------------------------------------------------------
extern "C" void kernel_launch(void* const* d_in, const int* in_sizes, int n_in,
                              void* d_out, int out_size)
{
    const float* stm  = (const float*)d_in[0];
    const float* wq   = (const float*)d_in[1];
    const float* wk   = (const float*)d_in[2];
    const float* wv   = (const float*)d_in[3];
    const float* wo   = (const float*)d_in[4];
    const float* cosv = (const float*)d_in[5];
    const float* sinv = (const float*)d_in[6];
    float* out = (float*)d_out;

    float *q, *k, *v;
    cudaGetSymbolAddress((void**)&q, g_q);
    cudaGetSymbolAddress((void**)&k, g_k);
    cudaGetSymbolAddress((void**)&v, g_v);
    unsigned short *xh, *xl, *wqh, *wql, *wkh, *wkl, *wvh, *wvl, *woh, *wol, *oh, *ol;
    cudaGetSymbolAddress((void**)&xh,  g_xh);  cudaGetSymbolAddress((void**)&xl,  g_xl);
    cudaGetSymbolAddress((void**)&wqh, g_wqh); cudaGetSymbolAddress((void**)&wql, g_wql);
    cudaGetSymbolAddress((void**)&wkh, g_wkh); cudaGetSymbolAddress((void**)&wkl, g_wkl);
    cudaGetSymbolAddress((void**)&wvh, g_wvh); cudaGetSymbolAddress((void**)&wvl, g_wvl);
    cudaGetSymbolAddress((void**)&woh, g_woh); cudaGetSymbolAddress((void**)&wol, g_wol);
    cudaGetSymbolAddress((void**)&oh,  g_oh);  cudaGetSymbolAddress((void**)&ol,  g_ol);
    unsigned short *qh2, *ql2, *kh2, *kl2, *vth, *vtl;
    cudaGetSymbolAddress((void**)&qh2, g_qh2); cudaGetSymbolAddress((void**)&ql2, g_ql2);
    cudaGetSymbolAddress((void**)&kh2, g_kh2); cudaGetSymbolAddress((void**)&kl2, g_kl2);
    cudaGetSymbolAddress((void**)&vth, g_vth); cudaGetSymbolAddress((void**)&vtl, g_vtl);

    cudaFuncSetAttribute(gemm_mma, cudaFuncAttributeMaxDynamicSharedMemorySize, GSMEM);
    cudaFuncSetAttribute(attn_mma, cudaFuncAttributeMaxDynamicSharedMemorySize, AT_SMEM);

    // Conversions
    split_kernel<<<MTOT*INNER/1024, 256>>>(stm, xh, xl, MTOT*INNER);
    transpose_split<<<dim3(INNER/32, INNER/32), dim3(32,8)>>>(wq, wqh, wql, INNER, INNER);
    transpose_split<<<dim3(KVIN/32,  INNER/32), dim3(32,8)>>>(wk, wkh, wkl, INNER, KVIN);
    transpose_split<<<dim3(KVIN/32,  INNER/32), dim3(32,8)>>>(wv, wvh, wvl, INNER, KVIN);
    transpose_split<<<dim3(INNER/32, INNER/32), dim3(32,8)>>>(wo, woh, wol, INNER, INNER);

    // QKV projections
    gemm_mma<<<dim3(INNER/128, MTOT/128), 256, GSMEM>>>(xh, xl, wqh, wql, q, INNER, INNER);
    gemm_mma<<<dim3(KVIN/128,  MTOT/128), 256, GSMEM>>>(xh, xl, wkh, wkl, k, KVIN,  INNER);
    gemm_mma<<<dim3(KVIN/128,  MTOT/128), 256, GSMEM>>>(xh, xl, wvh, wvl, v, KVIN,  INNER);

    // RoPE
    {
        int nq = Bb * Ts * Hq  * 64;
        int nk = Bb * Ts * Hkv * 64;
        rope_kernel<<<(nq + 255) / 256, 256>>>(q, cosv, sinv, Hq,  nq);
        rope_kernel<<<(nk + 255) / 256, 256>>>(k, cosv, sinv, Hkv, nk);
    }

    // Attention operand prep: relayout + split (+ transpose for V)
    relayout_split<<<(Bb*Ts*Hq*Dd/4 + 255)/256, 256>>>(q, qh2, ql2, Hq,  Bb*Ts*Hq*Dd/4);
    relayout_split<<<(Bb*Ts*Hkv*Dd/4 + 255)/256, 256>>>(k, kh2, kl2, Hkv, Bb*Ts*Hkv*Dd/4);
    vtrans_split<<<dim3(Ts/32, Dd/32, Bb*Hkv), dim3(32,8)>>>(v, vth, vtl);

    // Tensor-core attention (writes bf16 hi/lo directly)
    attn_mma<<<dim3(Ts/128, Hq, Bb), 256, AT_SMEM>>>(qh2, ql2, kh2, kl2, vth, vtl, oh, ol);

    // Output projection
    gemm_mma<<<dim3(INNER/128, MTOT/128), 256, GSMEM>>>(oh, ol, woh, wol, out, INNER, INNER);
}